// round 4
// baseline (speedup 1.0000x reference)
#include <cuda_runtime.h>
#include <mma.h>

using namespace nvcuda;

// ---------------------------------------------------------------------------
// HybridGNN: 2x GCNConv(+ReLU+BN) -> global mean pool -> concat rdkit ->
//            MLP (Linear+ReLU+BN) x2 -> Linear -> [G]
// Optimizations:
//   * aggregate-then-GEMM:  Â (X W) == (Â X) W
//   * per-launch padded-slot CSR (dst-keyed), reused by BOTH layers; gather
//     aggregation with register accumulation (no atomics)
//   * 3xTF32 wmma tensor-core GEMM for the two node-level GEMMs (fp32-level
//     accuracy via hi/lo split)
//   * BN1-apply folded into layer-2 gather; BN2-apply folded into pool/concat
// ---------------------------------------------------------------------------

namespace {
constexpr int F_DIM = 64;
constexpr int H1    = 128;
constexpr int HH    = 256;   // 2H
constexpr int RDK   = 200;
constexpr int ZD    = 456;   // 2H + R
constexpr int NMAX  = 100000;
constexpr int GMAX  = 4096;
constexpr int SLOTS = 160;
constexpr int OFCAP = 4096;
}

__device__ float g_dinv[NMAX];
__device__ int   g_degc[NMAX];
__device__ int   g_csr [(size_t)NMAX * SLOTS];
__device__ int   g_ovf [OFCAP];
__device__ int   g_ovfcnt;
__device__ float g_agg[(size_t)NMAX * H1];
__device__ float g_h  [(size_t)NMAX * HH];
__device__ float g_stats[2 * HH];
__device__ float g_coefA[HH];
__device__ float g_coefB[HH];
__device__ float g_pool[(size_t)GMAX * HH];
__device__ float g_cnt [GMAX];
__device__ float g_z   [(size_t)GMAX * ZD];
__device__ float g_z1  [(size_t)GMAX * HH];
__device__ float g_z2  [(size_t)GMAX * H1];

__device__ __forceinline__ void red4(float* p, float4 v) {
    asm volatile("red.global.add.v4.f32 [%0], {%1,%2,%3,%4};"
                 :: "l"(p), "f"(v.x), "f"(v.y), "f"(v.z), "f"(v.w)
                 : "memory");
}

// ---------------------------------------------------------------------------
// Utility
// ---------------------------------------------------------------------------
__global__ void k_fill(float* p, float v, int n) {
    int i = blockIdx.x * blockDim.x + threadIdx.x;
    if (i < n) p[i] = v;
}
__global__ void k_fill_int(int* p, int v, int n) {
    int i = blockIdx.x * blockDim.x + threadIdx.x;
    if (i < n) p[i] = v;
}

// ---------------------------------------------------------------------------
// CSR build
// ---------------------------------------------------------------------------
__global__ void k_csr_build(const int* __restrict__ row, const int* __restrict__ col,
                            int* __restrict__ cursor, int* __restrict__ csr,
                            int* __restrict__ ovf, int* __restrict__ ovfcnt, int E) {
    int e = blockIdx.x * blockDim.x + threadIdx.x;
    if (e >= E) return;
    int c = col[e];
    int slot = atomicAdd(&cursor[c], 1);
    if (slot < SLOTS) {
        csr[(size_t)c * SLOTS + slot] = row[e];
    } else {
        int o = atomicAdd(ovfcnt, 1);
        if (o < OFCAP) ovf[o] = e;
    }
}

__global__ void k_dinv(const int* __restrict__ deg, float* __restrict__ dinv, int N) {
    int i = blockIdx.x * blockDim.x + threadIdx.x;
    if (i < N) dinv[i] = rsqrtf((float)deg[i] + 1.0f);
}

// ---------------------------------------------------------------------------
// Gather aggregation (warp per node). Self loop folded into accumulator init.
// AFFINE: src values are transformed per-feature by a*v+b (BN apply folded in):
//   out = a (.) acc_raw + wsum * b,  wsum = dn^2 + sum(nrm)
// ---------------------------------------------------------------------------
template <int M, bool AFFINE>
__global__ void k_gather(const int* __restrict__ csr, const int* __restrict__ deg,
                         const float* __restrict__ dinv, const float* __restrict__ src,
                         const float* __restrict__ ca, const float* __restrict__ cb,
                         float* __restrict__ out, int N) {
    int warp = (blockIdx.x * blockDim.x + threadIdx.x) >> 5;
    int lane = threadIdx.x & 31;
    if (warp >= N) return;
    const int n = warp;
    int d = deg[n];
    if (d > SLOTS) d = SLOTS;
    const float dn = dinv[n];
    const int* list = csr + (size_t)n * SLOTS;
    float wsum = dn * dn;

    if constexpr (M == 128) {
        float4 acc = ((const float4*)(src + (size_t)n * M))[lane];
        acc.x *= wsum; acc.y *= wsum; acc.z *= wsum; acc.w *= wsum;
        for (int base = 0; base < d; base += 32) {
            int li = base + lane;
            int idx = (li < d) ? list[li] : 0;
            float dr = (li < d) ? dinv[idx] : 0.0f;
            int m = min(32, d - base);
            int j = 0;
            for (; j + 1 < m; j += 2) {
                int   r0 = __shfl_sync(0xffffffffu, idx, j);
                float n0 = __shfl_sync(0xffffffffu, dr, j) * dn;
                int   r1 = __shfl_sync(0xffffffffu, idx, j + 1);
                float n1 = __shfl_sync(0xffffffffu, dr, j + 1) * dn;
                wsum += n0 + n1;
                float4 v0 = ((const float4*)(src + (size_t)r0 * M))[lane];
                float4 v1 = ((const float4*)(src + (size_t)r1 * M))[lane];
                acc.x += n0 * v0.x + n1 * v1.x;
                acc.y += n0 * v0.y + n1 * v1.y;
                acc.z += n0 * v0.z + n1 * v1.z;
                acc.w += n0 * v0.w + n1 * v1.w;
            }
            if (j < m) {
                int   r0 = __shfl_sync(0xffffffffu, idx, j);
                float n0 = __shfl_sync(0xffffffffu, dr, j) * dn;
                wsum += n0;
                float4 v0 = ((const float4*)(src + (size_t)r0 * M))[lane];
                acc.x += n0 * v0.x; acc.y += n0 * v0.y;
                acc.z += n0 * v0.z; acc.w += n0 * v0.w;
            }
        }
        if constexpr (AFFINE) {
            float4 a4 = ((const float4*)ca)[lane];
            float4 b4 = ((const float4*)cb)[lane];
            acc.x = a4.x * acc.x + wsum * b4.x;
            acc.y = a4.y * acc.y + wsum * b4.y;
            acc.z = a4.z * acc.z + wsum * b4.z;
            acc.w = a4.w * acc.w + wsum * b4.w;
        }
        ((float4*)(out + (size_t)n * M))[lane] = acc;
    } else {  // M == 64
        float2 acc = ((const float2*)(src + (size_t)n * M))[lane];
        acc.x *= wsum; acc.y *= wsum;
        for (int base = 0; base < d; base += 32) {
            int li = base + lane;
            int idx = (li < d) ? list[li] : 0;
            float dr = (li < d) ? dinv[idx] : 0.0f;
            int m = min(32, d - base);
            int j = 0;
            for (; j + 1 < m; j += 2) {
                int   r0 = __shfl_sync(0xffffffffu, idx, j);
                float n0 = __shfl_sync(0xffffffffu, dr, j) * dn;
                int   r1 = __shfl_sync(0xffffffffu, idx, j + 1);
                float n1 = __shfl_sync(0xffffffffu, dr, j + 1) * dn;
                wsum += n0 + n1;
                float2 v0 = ((const float2*)(src + (size_t)r0 * M))[lane];
                float2 v1 = ((const float2*)(src + (size_t)r1 * M))[lane];
                acc.x += n0 * v0.x + n1 * v1.x;
                acc.y += n0 * v0.y + n1 * v1.y;
            }
            if (j < m) {
                int   r0 = __shfl_sync(0xffffffffu, idx, j);
                float n0 = __shfl_sync(0xffffffffu, dr, j) * dn;
                wsum += n0;
                float2 v0 = ((const float2*)(src + (size_t)r0 * M))[lane];
                acc.x += n0 * v0.x; acc.y += n0 * v0.y;
            }
        }
        if constexpr (AFFINE) {
            float2 a2 = ((const float2*)ca)[lane];
            float2 b2 = ((const float2*)cb)[lane];
            acc.x = a2.x * acc.x + wsum * b2.x;
            acc.y = a2.y * acc.y + wsum * b2.y;
        }
        ((float2*)(out + (size_t)n * M))[lane] = acc;
    }
}

// Overflow fallback (expected count 0)
template <int M, bool AFFINE>
__global__ void k_overflow(const int* __restrict__ row, const int* __restrict__ col,
                           const int* __restrict__ ovf, const int* __restrict__ ovfcnt,
                           const float* __restrict__ dinv,
                           const float* __restrict__ src,
                           const float* __restrict__ ca, const float* __restrict__ cb,
                           float* __restrict__ dst) {
    int cnt = *ovfcnt;
    if (cnt > OFCAP) cnt = OFCAP;
    for (int i = threadIdx.x; i < cnt * (M / 4); i += blockDim.x) {
        int e = ovf[i / (M / 4)];
        int l = i % (M / 4);
        int r = row[e], c = col[e];
        float nrm = dinv[r] * dinv[c];
        float4 v = ((const float4*)(src + (size_t)r * M))[l];
        if constexpr (AFFINE) {
            float4 a4 = ((const float4*)ca)[l];
            float4 b4 = ((const float4*)cb)[l];
            v.x = a4.x * v.x + b4.x; v.y = a4.y * v.y + b4.y;
            v.z = a4.z * v.z + b4.z; v.w = a4.w * v.w + b4.w;
        }
        v.x *= nrm; v.y *= nrm; v.z *= nrm; v.w *= nrm;
        red4(dst + (size_t)c * M + l * 4, v);
    }
}

// ---------------------------------------------------------------------------
// 3xTF32 wmma GEMM: C[N,M] = A[N,K] @ B[K,M], bias + ReLU epilogue.
// Requires K % 16 == 0, M % 128 == 0. Block 256 thr (8 warps), tile 128x128.
// Warp grid 2x4: each warp 64 rows x 32 cols = 4x2 wmma(16x16) fragments.
// ---------------------------------------------------------------------------
__launch_bounds__(256)
__global__ void k_gemm_tf32(const float* __restrict__ A, const float* __restrict__ B,
                            const float* __restrict__ bias, float* __restrict__ C,
                            int N, int K, int M) {
    constexpr int LDA = 20;    // 16 + 4 pad
    constexpr int LDB = 132;   // 128 + 4 pad
    __shared__ float Ah[128 * LDA];
    __shared__ float Al[128 * LDA];
    __shared__ float Bh[16 * LDB];
    __shared__ float Bl[16 * LDB];
    __shared__ float wbuf[8 * 256];

    const int tx   = threadIdx.x;
    const int warp = tx >> 5;
    const int lane = tx & 31;
    const int wr   = warp >> 2;            // 0..1
    const int wc   = warp & 3;             // 0..3
    const int row0 = blockIdx.x * 128;
    const int colT = blockIdx.y * 128;

    wmma::fragment<wmma::accumulator, 16, 16, 8, float> acc[4][2];
#pragma unroll
    for (int m = 0; m < 4; m++)
#pragma unroll
        for (int n = 0; n < 2; n++) wmma::fill_fragment(acc[m][n], 0.0f);

    for (int k0 = 0; k0 < K; k0 += 16) {
        // Load A tile 128x16 (fp32 -> hi/lo tf32)
#pragma unroll
        for (int i = 0; i < 2; i++) {
            int idx = tx * 2 + i;           // float4 id, 512 total
            int r   = idx >> 2;
            int kq  = (idx & 3) * 4;
            float4 v = make_float4(0.f, 0.f, 0.f, 0.f);
            int grow = row0 + r;
            if (grow < N) v = *(const float4*)&A[(size_t)grow * K + k0 + kq];
            float hx = wmma::__float_to_tf32(v.x);
            float hy = wmma::__float_to_tf32(v.y);
            float hz = wmma::__float_to_tf32(v.z);
            float hw = wmma::__float_to_tf32(v.w);
            Ah[r * LDA + kq + 0] = hx;
            Ah[r * LDA + kq + 1] = hy;
            Ah[r * LDA + kq + 2] = hz;
            Ah[r * LDA + kq + 3] = hw;
            Al[r * LDA + kq + 0] = wmma::__float_to_tf32(v.x - hx);
            Al[r * LDA + kq + 1] = wmma::__float_to_tf32(v.y - hy);
            Al[r * LDA + kq + 2] = wmma::__float_to_tf32(v.z - hz);
            Al[r * LDA + kq + 3] = wmma::__float_to_tf32(v.w - hw);
        }
        // Load B tile 16x128
#pragma unroll
        for (int i = 0; i < 2; i++) {
            int idx = tx * 2 + i;
            int kk  = idx >> 5;
            int cq  = (idx & 31) * 4;
            float4 v = *(const float4*)&B[(size_t)(k0 + kk) * M + colT + cq];
            float hx = wmma::__float_to_tf32(v.x);
            float hy = wmma::__float_to_tf32(v.y);
            float hz = wmma::__float_to_tf32(v.z);
            float hw = wmma::__float_to_tf32(v.w);
            Bh[kk * LDB + cq + 0] = hx;
            Bh[kk * LDB + cq + 1] = hy;
            Bh[kk * LDB + cq + 2] = hz;
            Bh[kk * LDB + cq + 3] = hw;
            Bl[kk * LDB + cq + 0] = wmma::__float_to_tf32(v.x - hx);
            Bl[kk * LDB + cq + 1] = wmma::__float_to_tf32(v.y - hy);
            Bl[kk * LDB + cq + 2] = wmma::__float_to_tf32(v.z - hz);
            Bl[kk * LDB + cq + 3] = wmma::__float_to_tf32(v.w - hw);
        }
        __syncthreads();

#pragma unroll
        for (int ks = 0; ks < 16; ks += 8) {
            wmma::fragment<wmma::matrix_b, 16, 16, 8, wmma::precision::tf32, wmma::row_major> bh[2], bl[2];
#pragma unroll
            for (int n = 0; n < 2; n++) {
                wmma::load_matrix_sync(bh[n], &Bh[ks * LDB + wc * 32 + n * 16], LDB);
                wmma::load_matrix_sync(bl[n], &Bl[ks * LDB + wc * 32 + n * 16], LDB);
            }
#pragma unroll
            for (int m = 0; m < 4; m++) {
                wmma::fragment<wmma::matrix_a, 16, 16, 8, wmma::precision::tf32, wmma::row_major> ah, al;
                wmma::load_matrix_sync(ah, &Ah[(wr * 64 + m * 16) * LDA + ks], LDA);
                wmma::load_matrix_sync(al, &Al[(wr * 64 + m * 16) * LDA + ks], LDA);
#pragma unroll
                for (int n = 0; n < 2; n++) {
                    wmma::mma_sync(acc[m][n], ah, bh[n], acc[m][n]);
                    wmma::mma_sync(acc[m][n], ah, bl[n], acc[m][n]);
                    wmma::mma_sync(acc[m][n], al, bh[n], acc[m][n]);
                }
            }
        }
        __syncthreads();
    }

    // Epilogue: per-fragment via per-warp smem buffer; bias + ReLU
    float* wb = &wbuf[warp * 256];
#pragma unroll
    for (int m = 0; m < 4; m++) {
#pragma unroll
        for (int n = 0; n < 2; n++) {
            wmma::store_matrix_sync(wb, acc[m][n], 16, wmma::mem_row_major);
            __syncwarp();
#pragma unroll
            for (int j = 0; j < 8; j++) {
                int idx = j * 32 + lane;
                int rr = idx >> 4, cc = idx & 15;
                int grow = row0 + wr * 64 + m * 16 + rr;
                int gcol = colT + wc * 32 + n * 16 + cc;
                if (grow < N)
                    C[(size_t)grow * M + gcol] = fmaxf(wb[idx] + bias[gcol], 0.0f);
            }
            __syncwarp();
        }
    }
}

// ---------------------------------------------------------------------------
// fp32 SGEMM for the small MLP-head GEMMs (handles K not multiple of 16)
// ---------------------------------------------------------------------------
template <bool BIAS_RELU>
__launch_bounds__(256, 2)
__global__ void k_gemm128(const float* __restrict__ A, const float* __restrict__ B,
                          const float* __restrict__ bias, float* __restrict__ C,
                          int N, int K, int M) {
    constexpr int BM = 128, BN = 128, KT = 16;
    __shared__ float As[KT][BM];
    __shared__ float Bs[KT][BN];

    const int row0 = blockIdx.x * BM;
    const int colT = blockIdx.y * BN;
    const int tx   = threadIdx.x;
    const int tcol = tx & 15;
    const int trow = tx >> 4;
    const int c0   = colT + tcol * 8;
    const int r0   = row0 + trow * 8;

    float acc[8][8];
#pragma unroll
    for (int r = 0; r < 8; r++)
#pragma unroll
        for (int c = 0; c < 8; c++) acc[r][c] = 0.0f;

    for (int k0 = 0; k0 < K; k0 += KT) {
#pragma unroll
        for (int i = 0; i < 2; i++) {
            int idx = tx + i * 256;
            int kk  = idx >> 5;
            int cq  = idx & 31;
            int k   = k0 + kk;
            float4 v = make_float4(0.f, 0.f, 0.f, 0.f);
            if (k < K) v = *(const float4*)&B[(size_t)k * M + colT + cq * 4];
            *(float4*)&Bs[kk][cq * 4] = v;
        }
#pragma unroll
        for (int i = 0; i < 2; i++) {
            int idx = tx + i * 256;
            int r   = idx >> 2;
            int kq  = idx & 3;
            int row = row0 + r;
            int k   = k0 + kq * 4;
            float4 v = make_float4(0.f, 0.f, 0.f, 0.f);
            if (row < N) {
                if (k + 3 < K) {
                    v = *(const float4*)&A[(size_t)row * K + k];
                } else {
                    float t0 = (k + 0 < K) ? A[(size_t)row * K + k + 0] : 0.f;
                    float t1 = (k + 1 < K) ? A[(size_t)row * K + k + 1] : 0.f;
                    float t2 = (k + 2 < K) ? A[(size_t)row * K + k + 2] : 0.f;
                    float t3 = (k + 3 < K) ? A[(size_t)row * K + k + 3] : 0.f;
                    v = make_float4(t0, t1, t2, t3);
                }
            }
            As[kq * 4 + 0][r] = v.x;
            As[kq * 4 + 1][r] = v.y;
            As[kq * 4 + 2][r] = v.z;
            As[kq * 4 + 3][r] = v.w;
        }
        __syncthreads();

#pragma unroll
        for (int kk = 0; kk < KT; kk++) {
            float a[8], b[8];
            *(float4*)&a[0] = *(const float4*)&As[kk][trow * 8];
            *(float4*)&a[4] = *(const float4*)&As[kk][trow * 8 + 4];
            *(float4*)&b[0] = *(const float4*)&Bs[kk][tcol * 8];
            *(float4*)&b[4] = *(const float4*)&Bs[kk][tcol * 8 + 4];
#pragma unroll
            for (int r = 0; r < 8; r++)
#pragma unroll
                for (int c = 0; c < 8; c++)
                    acc[r][c] += a[r] * b[c];
        }
        __syncthreads();
    }

    float bv[8];
    if constexpr (BIAS_RELU) {
        *(float4*)&bv[0] = *(const float4*)&bias[c0];
        *(float4*)&bv[4] = *(const float4*)&bias[c0 + 4];
    }

#pragma unroll
    for (int r = 0; r < 8; r++) {
        int row = r0 + r;
        if (row < N) {
            if constexpr (BIAS_RELU) {
#pragma unroll
                for (int c = 0; c < 8; c++)
                    acc[r][c] = fmaxf(acc[r][c] + bv[c], 0.0f);
            }
            *(float4*)&C[(size_t)row * M + c0]     = *(float4*)&acc[r][0];
            *(float4*)&C[(size_t)row * M + c0 + 4] = *(float4*)&acc[r][4];
        }
    }
}

// ---------------------------------------------------------------------------
// BatchNorm helpers
// ---------------------------------------------------------------------------
template <int M>
__global__ void k_bn_stats(const float* __restrict__ h, float* __restrict__ stats, int N) {
    int f = threadIdx.x;
    float s = 0.f, sq = 0.f;
    for (int n = blockIdx.x; n < N; n += gridDim.x) {
        float v = h[(size_t)n * M + f];
        s += v;
        sq += v * v;
    }
    atomicAdd(&stats[f], s);
    atomicAdd(&stats[M + f], sq);
}

// coefA = gamma * rsqrt(var + eps); coefB = beta - coefA * mu
template <int M>
__global__ void k_bn_coef(const float* __restrict__ stats,
                          const float* __restrict__ gamma, const float* __restrict__ beta,
                          float* __restrict__ ca, float* __restrict__ cb, int N) {
    int f = threadIdx.x + blockIdx.x * blockDim.x;
    if (f >= M) return;
    float inv_n = 1.0f / (float)N;
    float mu = stats[f] * inv_n;
    float var = stats[M + f] * inv_n - mu * mu;
    float a = gamma[f] * rsqrtf(var + 1e-5f);
    ca[f] = a;
    cb[f] = beta[f] - a * mu;
}

template <int M>
__global__ void k_bn_apply(float* __restrict__ h, const float* __restrict__ stats,
                           const float* __restrict__ gamma, const float* __restrict__ beta,
                           int N) {
    size_t i = (size_t)blockIdx.x * blockDim.x + threadIdx.x;
    if (i >= (size_t)N * M) return;
    int f = (int)(i % M);
    float inv_n = 1.0f / (float)N;
    float mu = stats[f] * inv_n;
    float var = stats[M + f] * inv_n - mu * mu;
    float sc = gamma[f] * rsqrtf(var + 1e-5f);
    h[i] = (h[i] - mu) * sc + beta[f];
}

// ---------------------------------------------------------------------------
// Global mean pool (raw h2) + concat with BN2-apply folded in
// ---------------------------------------------------------------------------
__global__ void k_pool_add(const float* __restrict__ h, const int* __restrict__ batch,
                           float* __restrict__ pool, float* __restrict__ cnt, int N) {
    size_t t = (size_t)blockIdx.x * blockDim.x + threadIdx.x;
    if (t >= (size_t)N * (HH / 4)) return;
    int n  = (int)(t >> 6);
    int f4 = (int)(t & 63);
    int g = batch[n];
    float4 v = ((const float4*)(h + (size_t)n * HH))[f4];
    red4(pool + (size_t)g * HH + f4 * 4, v);
    if (f4 == 0) atomicAdd(&cnt[g], 1.0f);
}

__global__ void k_concat(const float* __restrict__ pool, const float* __restrict__ cnt,
                         const float* __restrict__ ca, const float* __restrict__ cb,
                         const float* __restrict__ rdkit, float* __restrict__ z, int G) {
    int t = blockIdx.x * blockDim.x + threadIdx.x;
    if (t >= G * ZD) return;
    int g = t / ZD, f = t % ZD;
    float out;
    if (f < HH) {
        float mean = pool[(size_t)g * HH + f] / fmaxf(cnt[g], 1.0f);
        out = ca[f] * mean + cb[f];   // BN2 apply commutes with mean
    } else {
        out = rdkit[(size_t)g * RDK + (f - HH)];
    }
    z[t] = out;
}

// ---------------------------------------------------------------------------
// Final projection
// ---------------------------------------------------------------------------
__global__ void k_final(const float* __restrict__ z2, const float* __restrict__ w,
                        const float* __restrict__ b, float* __restrict__ out, int G) {
    int warp = (blockIdx.x * blockDim.x + threadIdx.x) >> 5;
    int lane = threadIdx.x & 31;
    if (warp >= G) return;
    const float* zr = z2 + (size_t)warp * H1;
    float s = zr[lane] * w[lane] + zr[lane + 32] * w[lane + 32] +
              zr[lane + 64] * w[lane + 64] + zr[lane + 96] * w[lane + 96];
#pragma unroll
    for (int off = 16; off > 0; off >>= 1)
        s += __shfl_down_sync(0xffffffffu, s, off);
    if (lane == 0) out[warp] = s + b[0];
}

// ---------------------------------------------------------------------------
// Launch
// ---------------------------------------------------------------------------
extern "C" void kernel_launch(void* const* d_in, const int* in_sizes, int n_in,
                              void* d_out, int out_size) {
    const float* x      = (const float*)d_in[0];
    const int*   ei     = (const int*)d_in[1];
    const int*   batch  = (const int*)d_in[2];
    const float* rdkit  = (const float*)d_in[3];
    const float* W1  = (const float*)d_in[4];
    const float* b1  = (const float*)d_in[5];
    const float* gm1 = (const float*)d_in[6];
    const float* be1 = (const float*)d_in[7];
    const float* W2  = (const float*)d_in[8];
    const float* b2  = (const float*)d_in[9];
    const float* gm2 = (const float*)d_in[10];
    const float* be2 = (const float*)d_in[11];
    const float* mW1 = (const float*)d_in[12];
    const float* mb1 = (const float*)d_in[13];
    const float* mg1 = (const float*)d_in[14];
    const float* mbe1= (const float*)d_in[15];
    const float* mW2 = (const float*)d_in[16];
    const float* mb2 = (const float*)d_in[17];
    const float* mg2 = (const float*)d_in[18];
    const float* mbe2= (const float*)d_in[19];
    const float* mW3 = (const float*)d_in[20];
    const float* mb3 = (const float*)d_in[21];
    float* out = (float*)d_out;

    const int N = in_sizes[2];
    const int E = in_sizes[1] / 2;
    const int G = in_sizes[3] / RDK;
    const int* row = ei;
    const int* col = ei + E;

    float *dinv, *agg, *h, *stats, *ca, *cb, *pool, *cnt, *z, *z1, *z2;
    int *degc, *csr, *ovf, *ovfcnt;
    cudaGetSymbolAddress((void**)&dinv,  g_dinv);
    cudaGetSymbolAddress((void**)&degc,  g_degc);
    cudaGetSymbolAddress((void**)&csr,   g_csr);
    cudaGetSymbolAddress((void**)&ovf,   g_ovf);
    cudaGetSymbolAddress((void**)&ovfcnt,g_ovfcnt);
    cudaGetSymbolAddress((void**)&agg,   g_agg);
    cudaGetSymbolAddress((void**)&h,     g_h);
    cudaGetSymbolAddress((void**)&stats, g_stats);
    cudaGetSymbolAddress((void**)&ca,    g_coefA);
    cudaGetSymbolAddress((void**)&cb,    g_coefB);
    cudaGetSymbolAddress((void**)&pool,  g_pool);
    cudaGetSymbolAddress((void**)&cnt,   g_cnt);
    cudaGetSymbolAddress((void**)&z,     g_z);
    cudaGetSymbolAddress((void**)&z1,    g_z1);
    cudaGetSymbolAddress((void**)&z2,    g_z2);

    auto cdiv = [](long long a, long long b) { return (int)((a + b - 1) / b); };

    // --- CSR build (shared by both layers) + dinv ---
    k_fill_int<<<cdiv(N, 256), 256>>>(degc, 0, N);
    k_fill_int<<<1, 32>>>(ovfcnt, 0, 1);
    k_csr_build<<<cdiv(E, 256), 256>>>(row, col, degc, csr, ovf, ovfcnt, E);
    k_dinv<<<cdiv(N, 256), 256>>>(degc, dinv, N);

    // --- layer 1: aggX = Â x ; h1 = relu(aggX @ W1 + b1) ; BN1 stats+coef ---
    k_gather<F_DIM, false><<<cdiv((long long)N * 32, 256), 256>>>(
        csr, degc, dinv, x, nullptr, nullptr, agg, N);
    k_overflow<F_DIM, false><<<1, 256>>>(row, col, ovf, ovfcnt, dinv, x, nullptr, nullptr, agg);
    {
        dim3 grid(cdiv(N, 128), 1);
        k_gemm_tf32<<<grid, 256>>>(agg, W1, b1, h, N, F_DIM, H1);
    }
    k_fill<<<1, 256>>>(stats, 0.0f, 2 * H1);
    k_bn_stats<H1><<<512, H1>>>(h, stats, N);
    k_bn_coef<H1><<<1, H1>>>(stats, gm1, be1, ca, cb, N);

    // --- layer 2: agg2 = Â BN1(h1) (affine folded into gather) ; GEMM ; BN2 ---
    k_gather<H1, true><<<cdiv((long long)N * 32, 256), 256>>>(
        csr, degc, dinv, h, ca, cb, agg, N);
    k_overflow<H1, true><<<1, 256>>>(row, col, ovf, ovfcnt, dinv, h, ca, cb, agg);
    {
        dim3 grid(cdiv(N, 128), HH / 128);
        k_gemm_tf32<<<grid, 256>>>(agg, W2, b2, h, N, H1, HH);
    }
    k_fill<<<2, 256>>>(stats, 0.0f, 2 * HH);
    k_bn_stats<HH><<<512, HH>>>(h, stats, N);
    k_bn_coef<HH><<<1, HH>>>(stats, gm2, be2, ca, cb, N);

    // --- global mean pool (raw h2) + concat (BN2 apply folded) ---
    k_fill<<<cdiv((long long)G * HH, 256), 256>>>(pool, 0.0f, G * HH);
    k_fill<<<cdiv(G, 256), 256>>>(cnt, 0.0f, G);
    k_pool_add<<<cdiv((long long)N * (HH / 4), 256), 256>>>(h, batch, pool, cnt, N);
    k_concat<<<cdiv((long long)G * ZD, 256), 256>>>(pool, cnt, ca, cb, rdkit, z, G);

    // --- MLP head (small; fp32) ---
    {
        dim3 grid(cdiv(G, 128), HH / 128);
        k_gemm128<true><<<grid, 256>>>(z, mW1, mb1, z1, G, ZD, HH);
    }
    k_fill<<<2, 256>>>(stats, 0.0f, 2 * HH);
    k_bn_stats<HH><<<256, HH>>>(z1, stats, G);
    k_bn_apply<HH><<<cdiv((long long)G * HH, 256), 256>>>(z1, stats, mg1, mbe1, G);

    {
        dim3 grid(cdiv(G, 128), 1);
        k_gemm128<true><<<grid, 256>>>(z1, mW2, mb2, z2, G, HH, H1);
    }
    k_fill<<<1, 256>>>(stats, 0.0f, 2 * H1);
    k_bn_stats<H1><<<256, H1>>>(z2, stats, G);
    k_bn_apply<H1><<<cdiv((long long)G * H1, 256), 256>>>(z2, stats, mg2, mbe2, G);

    k_final<<<cdiv((long long)G * 32, 256), 256>>>(z2, mW3, mb3, out, G);
}

// round 5
// speedup vs baseline: 1.3077x; 1.3077x over previous
#include <cuda_runtime.h>

// ---------------------------------------------------------------------------
// HybridGNN: 2x GCNConv(+ReLU+BN) -> global mean pool -> concat rdkit ->
//            MLP (Linear+ReLU+BN) x2 -> Linear -> [G]
// Optimizations:
//   * aggregate-then-GEMM:  Â (X W) == (Â X) W
//   * padded-slot CSR (dst-keyed) built per launch, reused by BOTH layers;
//     register-accumulating gather (no atomics)
//   * BN1-apply folded into layer-2 gather; BN2-apply folded into concat
//   * BN-stats and mean-pool fused into GEMM epilogues; h2 never stored
// ---------------------------------------------------------------------------

namespace {
constexpr int F_DIM = 64;
constexpr int H1    = 128;
constexpr int HH    = 256;   // 2H
constexpr int RDK   = 200;
constexpr int ZD    = 456;   // 2H + R
constexpr int NMAX  = 100000;
constexpr int GMAX  = 4096;
constexpr int SLOTS = 96;
constexpr int OFCAP = 4096;
}

__device__ float g_dinv[NMAX];
__device__ int   g_degc[NMAX];
__device__ int   g_csr [(size_t)NMAX * SLOTS];
__device__ int   g_ovf [OFCAP];
__device__ int   g_ovfcnt;
__device__ float g_agg[(size_t)NMAX * H1];
__device__ float g_h  [(size_t)NMAX * H1];   // h1 only (h2 never materialized)
__device__ float g_stats[2 * HH];
__device__ float g_coefA[HH];
__device__ float g_coefB[HH];
__device__ float g_pool[(size_t)GMAX * HH];
__device__ float g_cnt [GMAX];
__device__ float g_z   [(size_t)GMAX * ZD];
__device__ float g_z1  [(size_t)GMAX * HH];
__device__ float g_z2  [(size_t)GMAX * H1];

__device__ __forceinline__ void red4(float* p, float4 v) {
    asm volatile("red.global.add.v4.f32 [%0], {%1,%2,%3,%4};"
                 :: "l"(p), "f"(v.x), "f"(v.y), "f"(v.z), "f"(v.w)
                 : "memory");
}

// ---------------------------------------------------------------------------
// Utility
// ---------------------------------------------------------------------------
__global__ void k_fill(float* p, float v, int n) {
    int i = blockIdx.x * blockDim.x + threadIdx.x;
    if (i < n) p[i] = v;
}
__global__ void k_fill_int(int* p, int v, int n) {
    int i = blockIdx.x * blockDim.x + threadIdx.x;
    if (i < n) p[i] = v;
}
__global__ void k_cnt(const int* __restrict__ batch, float* __restrict__ cnt, int N) {
    int i = blockIdx.x * blockDim.x + threadIdx.x;
    if (i < N) atomicAdd(&cnt[batch[i]], 1.0f);
}

// ---------------------------------------------------------------------------
// CSR build
// ---------------------------------------------------------------------------
__global__ void k_csr_build(const int* __restrict__ row, const int* __restrict__ col,
                            int* __restrict__ cursor, int* __restrict__ csr,
                            int* __restrict__ ovf, int* __restrict__ ovfcnt, int E) {
    int e = blockIdx.x * blockDim.x + threadIdx.x;
    if (e >= E) return;
    int c = col[e];
    int slot = atomicAdd(&cursor[c], 1);
    if (slot < SLOTS) {
        csr[(size_t)c * SLOTS + slot] = row[e];
    } else {
        int o = atomicAdd(ovfcnt, 1);
        if (o < OFCAP) ovf[o] = e;
    }
}

__global__ void k_dinv(const int* __restrict__ deg, float* __restrict__ dinv, int N) {
    int i = blockIdx.x * blockDim.x + threadIdx.x;
    if (i < N) dinv[i] = rsqrtf((float)deg[i] + 1.0f);
}

// ---------------------------------------------------------------------------
// Gather aggregation (warp per node); self loop in accumulator init.
// AFFINE folds BN apply of the SOURCE features:
//   out = a (.) acc_raw + wsum * b,   wsum = dn^2 + sum(nrm)
// ---------------------------------------------------------------------------
template <int M, bool AFFINE>
__global__ void k_gather(const int* __restrict__ csr, const int* __restrict__ deg,
                         const float* __restrict__ dinv, const float* __restrict__ src,
                         const float* __restrict__ ca, const float* __restrict__ cb,
                         float* __restrict__ out, int N) {
    int warp = (blockIdx.x * blockDim.x + threadIdx.x) >> 5;
    int lane = threadIdx.x & 31;
    if (warp >= N) return;
    const int n = warp;
    int d = deg[n];
    if (d > SLOTS) d = SLOTS;
    const float dn = dinv[n];
    const int* list = csr + (size_t)n * SLOTS;
    float wsum = dn * dn;

    if constexpr (M == 128) {
        float4 acc = ((const float4*)(src + (size_t)n * M))[lane];
        acc.x *= wsum; acc.y *= wsum; acc.z *= wsum; acc.w *= wsum;
        for (int base = 0; base < d; base += 32) {
            int li = base + lane;
            int idx = (li < d) ? list[li] : 0;
            float dr = (li < d) ? dinv[idx] : 0.0f;
            int m = min(32, d - base);
            int j = 0;
            for (; j + 1 < m; j += 2) {
                int   r0 = __shfl_sync(0xffffffffu, idx, j);
                float n0 = __shfl_sync(0xffffffffu, dr, j) * dn;
                int   r1 = __shfl_sync(0xffffffffu, idx, j + 1);
                float n1 = __shfl_sync(0xffffffffu, dr, j + 1) * dn;
                wsum += n0 + n1;
                float4 v0 = ((const float4*)(src + (size_t)r0 * M))[lane];
                float4 v1 = ((const float4*)(src + (size_t)r1 * M))[lane];
                acc.x += n0 * v0.x + n1 * v1.x;
                acc.y += n0 * v0.y + n1 * v1.y;
                acc.z += n0 * v0.z + n1 * v1.z;
                acc.w += n0 * v0.w + n1 * v1.w;
            }
            if (j < m) {
                int   r0 = __shfl_sync(0xffffffffu, idx, j);
                float n0 = __shfl_sync(0xffffffffu, dr, j) * dn;
                wsum += n0;
                float4 v0 = ((const float4*)(src + (size_t)r0 * M))[lane];
                acc.x += n0 * v0.x; acc.y += n0 * v0.y;
                acc.z += n0 * v0.z; acc.w += n0 * v0.w;
            }
        }
        if constexpr (AFFINE) {
            float4 a4 = ((const float4*)ca)[lane];
            float4 b4 = ((const float4*)cb)[lane];
            acc.x = a4.x * acc.x + wsum * b4.x;
            acc.y = a4.y * acc.y + wsum * b4.y;
            acc.z = a4.z * acc.z + wsum * b4.z;
            acc.w = a4.w * acc.w + wsum * b4.w;
        }
        ((float4*)(out + (size_t)n * M))[lane] = acc;
    } else {  // M == 64
        float2 acc = ((const float2*)(src + (size_t)n * M))[lane];
        acc.x *= wsum; acc.y *= wsum;
        for (int base = 0; base < d; base += 32) {
            int li = base + lane;
            int idx = (li < d) ? list[li] : 0;
            float dr = (li < d) ? dinv[idx] : 0.0f;
            int m = min(32, d - base);
            int j = 0;
            for (; j + 1 < m; j += 2) {
                int   r0 = __shfl_sync(0xffffffffu, idx, j);
                float n0 = __shfl_sync(0xffffffffu, dr, j) * dn;
                int   r1 = __shfl_sync(0xffffffffu, idx, j + 1);
                float n1 = __shfl_sync(0xffffffffu, dr, j + 1) * dn;
                wsum += n0 + n1;
                float2 v0 = ((const float2*)(src + (size_t)r0 * M))[lane];
                float2 v1 = ((const float2*)(src + (size_t)r1 * M))[lane];
                acc.x += n0 * v0.x + n1 * v1.x;
                acc.y += n0 * v0.y + n1 * v1.y;
            }
            if (j < m) {
                int   r0 = __shfl_sync(0xffffffffu, idx, j);
                float n0 = __shfl_sync(0xffffffffu, dr, j) * dn;
                wsum += n0;
                float2 v0 = ((const float2*)(src + (size_t)r0 * M))[lane];
                acc.x += n0 * v0.x; acc.y += n0 * v0.y;
            }
        }
        if constexpr (AFFINE) {
            float2 a2 = ((const float2*)ca)[lane];
            float2 b2 = ((const float2*)cb)[lane];
            acc.x = a2.x * acc.x + wsum * b2.x;
            acc.y = a2.y * acc.y + wsum * b2.y;
        }
        ((float2*)(out + (size_t)n * M))[lane] = acc;
    }
}

// Overflow fallback (expected count 0)
template <int M, bool AFFINE>
__global__ void k_overflow(const int* __restrict__ row, const int* __restrict__ col,
                           const int* __restrict__ ovf, const int* __restrict__ ovfcnt,
                           const float* __restrict__ dinv,
                           const float* __restrict__ src,
                           const float* __restrict__ ca, const float* __restrict__ cb,
                           float* __restrict__ dst) {
    int cnt = *ovfcnt;
    if (cnt > OFCAP) cnt = OFCAP;
    for (int i = threadIdx.x; i < cnt * (M / 4); i += blockDim.x) {
        int e = ovf[i / (M / 4)];
        int l = i % (M / 4);
        int r = row[e], c = col[e];
        float nrm = dinv[r] * dinv[c];
        float4 v = ((const float4*)(src + (size_t)r * M))[l];
        if constexpr (AFFINE) {
            float4 a4 = ((const float4*)ca)[l];
            float4 b4 = ((const float4*)cb)[l];
            v.x = a4.x * v.x + b4.x; v.y = a4.y * v.y + b4.y;
            v.z = a4.z * v.z + b4.z; v.w = a4.w * v.w + b4.w;
        }
        v.x *= nrm; v.y *= nrm; v.z *= nrm; v.w *= nrm;
        red4(dst + (size_t)c * M + l * 4, v);
    }
}

// ---------------------------------------------------------------------------
// fp32 SGEMM: C[N,M] = relu(A[N,K] @ B[K,M] + bias), with optional fused:
//   STATS: per-column sum/sumsq atomics into stats[2*M]
//   POOL:  per-row red4 into pool[batch[row]*M + col]
//   STORE: write C
// 128x128 tile, 256 threads, 8x8 per thread, KT=16.
// ---------------------------------------------------------------------------
template <bool STATS, bool POOL, bool STORE>
__launch_bounds__(256, 2)
__global__ void k_gemm128(const float* __restrict__ A, const float* __restrict__ B,
                          const float* __restrict__ bias, float* __restrict__ C,
                          const int* __restrict__ batch, float* __restrict__ pool,
                          float* __restrict__ stats,
                          int N, int K, int M) {
    constexpr int BM = 128, BN = 128, KT = 16;
    __shared__ float As[KT][BM];
    __shared__ float Bs[KT][BN];

    const int row0 = blockIdx.x * BM;
    const int colT = blockIdx.y * BN;
    const int tx   = threadIdx.x;
    const int tcol = tx & 15;
    const int trow = tx >> 4;
    const int c0   = colT + tcol * 8;
    const int r0   = row0 + trow * 8;

    float acc[8][8];
#pragma unroll
    for (int r = 0; r < 8; r++)
#pragma unroll
        for (int c = 0; c < 8; c++) acc[r][c] = 0.0f;

    for (int k0 = 0; k0 < K; k0 += KT) {
#pragma unroll
        for (int i = 0; i < 2; i++) {
            int idx = tx + i * 256;
            int kk  = idx >> 5;
            int cq  = idx & 31;
            int k   = k0 + kk;
            float4 v = make_float4(0.f, 0.f, 0.f, 0.f);
            if (k < K) v = *(const float4*)&B[(size_t)k * M + colT + cq * 4];
            *(float4*)&Bs[kk][cq * 4] = v;
        }
#pragma unroll
        for (int i = 0; i < 2; i++) {
            int idx = tx + i * 256;
            int r   = idx >> 2;
            int kq  = idx & 3;
            int row = row0 + r;
            int k   = k0 + kq * 4;
            float4 v = make_float4(0.f, 0.f, 0.f, 0.f);
            if (row < N) {
                if (k + 3 < K) {
                    v = *(const float4*)&A[(size_t)row * K + k];
                } else {
                    float t0 = (k + 0 < K) ? A[(size_t)row * K + k + 0] : 0.f;
                    float t1 = (k + 1 < K) ? A[(size_t)row * K + k + 1] : 0.f;
                    float t2 = (k + 2 < K) ? A[(size_t)row * K + k + 2] : 0.f;
                    float t3 = (k + 3 < K) ? A[(size_t)row * K + k + 3] : 0.f;
                    v = make_float4(t0, t1, t2, t3);
                }
            }
            As[kq * 4 + 0][r] = v.x;
            As[kq * 4 + 1][r] = v.y;
            As[kq * 4 + 2][r] = v.z;
            As[kq * 4 + 3][r] = v.w;
        }
        __syncthreads();

#pragma unroll
        for (int kk = 0; kk < KT; kk++) {
            float a[8], b[8];
            *(float4*)&a[0] = *(const float4*)&As[kk][trow * 8];
            *(float4*)&a[4] = *(const float4*)&As[kk][trow * 8 + 4];
            *(float4*)&b[0] = *(const float4*)&Bs[kk][tcol * 8];
            *(float4*)&b[4] = *(const float4*)&Bs[kk][tcol * 8 + 4];
#pragma unroll
            for (int r = 0; r < 8; r++)
#pragma unroll
                for (int c = 0; c < 8; c++)
                    acc[r][c] += a[r] * b[c];
        }
        __syncthreads();
    }

    // Epilogue: bias + ReLU (+ stats / pool / store)
    float bv[8];
    *(float4*)&bv[0] = *(const float4*)&bias[c0];
    *(float4*)&bv[4] = *(const float4*)&bias[c0 + 4];

    float s_part[8], q_part[8];
    if constexpr (STATS) {
#pragma unroll
        for (int c = 0; c < 8; c++) { s_part[c] = 0.f; q_part[c] = 0.f; }
    }

#pragma unroll
    for (int r = 0; r < 8; r++) {
        int row = r0 + r;
        if (row < N) {
#pragma unroll
            for (int c = 0; c < 8; c++)
                acc[r][c] = fmaxf(acc[r][c] + bv[c], 0.0f);
            if constexpr (STORE) {
                *(float4*)&C[(size_t)row * M + c0]     = *(float4*)&acc[r][0];
                *(float4*)&C[(size_t)row * M + c0 + 4] = *(float4*)&acc[r][4];
            }
            if constexpr (STATS) {
#pragma unroll
                for (int c = 0; c < 8; c++) {
                    s_part[c] += acc[r][c];
                    q_part[c] += acc[r][c] * acc[r][c];
                }
            }
            if constexpr (POOL) {
                int g = batch[row];
                red4(pool + (size_t)g * M + c0,     *(float4*)&acc[r][0]);
                red4(pool + (size_t)g * M + c0 + 4, *(float4*)&acc[r][4]);
            }
        }
    }

    if constexpr (STATS) {
        // reuse As (sum) and Bs (sumsq): [16 trows][128 cols]
        *(float4*)&As[trow][tcol * 8]     = *(float4*)&s_part[0];
        *(float4*)&As[trow][tcol * 8 + 4] = *(float4*)&s_part[4];
        *(float4*)&Bs[trow][tcol * 8]     = *(float4*)&q_part[0];
        *(float4*)&Bs[trow][tcol * 8 + 4] = *(float4*)&q_part[4];
        __syncthreads();
#pragma unroll
        for (int st = 8; st >= 1; st >>= 1) {
            if (trow < st) {
#pragma unroll
                for (int c = 0; c < 8; c++) {
                    As[trow][tcol * 8 + c] += As[trow + st][tcol * 8 + c];
                    Bs[trow][tcol * 8 + c] += Bs[trow + st][tcol * 8 + c];
                }
            }
            __syncthreads();
        }
        if (trow == 0) {
#pragma unroll
            for (int c = 0; c < 8; c++) {
                atomicAdd(&stats[c0 + c],     As[0][tcol * 8 + c]);
                atomicAdd(&stats[M + c0 + c], Bs[0][tcol * 8 + c]);
            }
        }
    }
}

// ---------------------------------------------------------------------------
// BatchNorm helpers
// ---------------------------------------------------------------------------
template <int M>
__global__ void k_bn_coef(const float* __restrict__ stats,
                          const float* __restrict__ gamma, const float* __restrict__ beta,
                          float* __restrict__ ca, float* __restrict__ cb, int N) {
    int f = threadIdx.x + blockIdx.x * blockDim.x;
    if (f >= M) return;
    float inv_n = 1.0f / (float)N;
    float mu = stats[f] * inv_n;
    float var = stats[M + f] * inv_n - mu * mu;
    float a = gamma[f] * rsqrtf(var + 1e-5f);
    ca[f] = a;
    cb[f] = beta[f] - a * mu;
}

template <int M>
__global__ void k_bn_apply(float* __restrict__ h, const float* __restrict__ stats,
                           const float* __restrict__ gamma, const float* __restrict__ beta,
                           int N) {
    size_t i = (size_t)blockIdx.x * blockDim.x + threadIdx.x;
    if (i >= (size_t)N * M) return;
    int f = (int)(i % M);
    float inv_n = 1.0f / (float)N;
    float mu = stats[f] * inv_n;
    float var = stats[M + f] * inv_n - mu * mu;
    float sc = gamma[f] * rsqrtf(var + 1e-5f);
    h[i] = (h[i] - mu) * sc + beta[f];
}

// ---------------------------------------------------------------------------
// Concat (mean + BN2-apply folded) with rdkit features
// ---------------------------------------------------------------------------
__global__ void k_concat(const float* __restrict__ pool, const float* __restrict__ cnt,
                         const float* __restrict__ ca, const float* __restrict__ cb,
                         const float* __restrict__ rdkit, float* __restrict__ z, int G) {
    int t = blockIdx.x * blockDim.x + threadIdx.x;
    if (t >= G * ZD) return;
    int g = t / ZD, f = t % ZD;
    float out;
    if (f < HH) {
        float mean = pool[(size_t)g * HH + f] / fmaxf(cnt[g], 1.0f);
        out = ca[f] * mean + cb[f];
    } else {
        out = rdkit[(size_t)g * RDK + (f - HH)];
    }
    z[t] = out;
}

// ---------------------------------------------------------------------------
// Final projection
// ---------------------------------------------------------------------------
__global__ void k_final(const float* __restrict__ z2, const float* __restrict__ w,
                        const float* __restrict__ b, float* __restrict__ out, int G) {
    int warp = (blockIdx.x * blockDim.x + threadIdx.x) >> 5;
    int lane = threadIdx.x & 31;
    if (warp >= G) return;
    const float* zr = z2 + (size_t)warp * H1;
    float s = zr[lane] * w[lane] + zr[lane + 32] * w[lane + 32] +
              zr[lane + 64] * w[lane + 64] + zr[lane + 96] * w[lane + 96];
#pragma unroll
    for (int off = 16; off > 0; off >>= 1)
        s += __shfl_down_sync(0xffffffffu, s, off);
    if (lane == 0) out[warp] = s + b[0];
}

// ---------------------------------------------------------------------------
// Launch
// ---------------------------------------------------------------------------
extern "C" void kernel_launch(void* const* d_in, const int* in_sizes, int n_in,
                              void* d_out, int out_size) {
    const float* x      = (const float*)d_in[0];
    const int*   ei     = (const int*)d_in[1];
    const int*   batch  = (const int*)d_in[2];
    const float* rdkit  = (const float*)d_in[3];
    const float* W1  = (const float*)d_in[4];
    const float* b1  = (const float*)d_in[5];
    const float* gm1 = (const float*)d_in[6];
    const float* be1 = (const float*)d_in[7];
    const float* W2  = (const float*)d_in[8];
    const float* b2  = (const float*)d_in[9];
    const float* gm2 = (const float*)d_in[10];
    const float* be2 = (const float*)d_in[11];
    const float* mW1 = (const float*)d_in[12];
    const float* mb1 = (const float*)d_in[13];
    const float* mg1 = (const float*)d_in[14];
    const float* mbe1= (const float*)d_in[15];
    const float* mW2 = (const float*)d_in[16];
    const float* mb2 = (const float*)d_in[17];
    const float* mg2 = (const float*)d_in[18];
    const float* mbe2= (const float*)d_in[19];
    const float* mW3 = (const float*)d_in[20];
    const float* mb3 = (const float*)d_in[21];
    float* out = (float*)d_out;

    const int N = in_sizes[2];
    const int E = in_sizes[1] / 2;
    const int G = in_sizes[3] / RDK;
    const int* row = ei;
    const int* col = ei + E;

    float *dinv, *agg, *h, *stats, *ca, *cb, *pool, *cnt, *z, *z1, *z2;
    int *degc, *csr, *ovf, *ovfcnt;
    cudaGetSymbolAddress((void**)&dinv,  g_dinv);
    cudaGetSymbolAddress((void**)&degc,  g_degc);
    cudaGetSymbolAddress((void**)&csr,   g_csr);
    cudaGetSymbolAddress((void**)&ovf,   g_ovf);
    cudaGetSymbolAddress((void**)&ovfcnt,g_ovfcnt);
    cudaGetSymbolAddress((void**)&agg,   g_agg);
    cudaGetSymbolAddress((void**)&h,     g_h);
    cudaGetSymbolAddress((void**)&stats, g_stats);
    cudaGetSymbolAddress((void**)&ca,    g_coefA);
    cudaGetSymbolAddress((void**)&cb,    g_coefB);
    cudaGetSymbolAddress((void**)&pool,  g_pool);
    cudaGetSymbolAddress((void**)&cnt,   g_cnt);
    cudaGetSymbolAddress((void**)&z,     g_z);
    cudaGetSymbolAddress((void**)&z1,    g_z1);
    cudaGetSymbolAddress((void**)&z2,    g_z2);

    auto cdiv = [](long long a, long long b) { return (int)((a + b - 1) / b); };

    // --- CSR build (shared by both layers) + dinv ---
    k_fill_int<<<cdiv(N, 256), 256>>>(degc, 0, N);
    k_fill_int<<<1, 32>>>(ovfcnt, 0, 1);
    k_csr_build<<<cdiv(E, 256), 256>>>(row, col, degc, csr, ovf, ovfcnt, E);
    k_dinv<<<cdiv(N, 256), 256>>>(degc, dinv, N);

    // --- layer 1: aggX = Â x ; h1 = relu(aggX @ W1 + b1) [stats fused] ---
    k_gather<F_DIM, false><<<cdiv((long long)N * 32, 256), 256>>>(
        csr, degc, dinv, x, nullptr, nullptr, agg, N);
    k_overflow<F_DIM, false><<<1, 256>>>(row, col, ovf, ovfcnt, dinv, x, nullptr, nullptr, agg);
    k_fill<<<1, 256>>>(stats, 0.0f, 2 * H1);
    {
        dim3 grid(cdiv(N, 128), 1);
        k_gemm128<true, false, true><<<grid, 256>>>(agg, W1, b1, h, nullptr, nullptr,
                                                    stats, N, F_DIM, H1);
    }
    k_bn_coef<H1><<<1, H1>>>(stats, gm1, be1, ca, cb, N);

    // --- layer 2: agg2 = Â BN1(h1) ; gemm2 with fused stats+pool, no store ---
    k_gather<H1, true><<<cdiv((long long)N * 32, 256), 256>>>(
        csr, degc, dinv, h, ca, cb, agg, N);
    k_overflow<H1, true><<<1, 256>>>(row, col, ovf, ovfcnt, dinv, h, ca, cb, agg);
    k_fill<<<2, 256>>>(stats, 0.0f, 2 * HH);
    k_fill<<<cdiv((long long)G * HH, 256), 256>>>(pool, 0.0f, G * HH);
    k_fill<<<cdiv(G, 256), 256>>>(cnt, 0.0f, G);
    k_cnt<<<cdiv(N, 256), 256>>>(batch, cnt, N);
    {
        dim3 grid(cdiv(N, 128), HH / 128);
        k_gemm128<true, true, false><<<grid, 256>>>(agg, W2, b2, nullptr, batch, pool,
                                                    stats, N, H1, HH);
    }
    k_bn_coef<HH><<<1, HH>>>(stats, gm2, be2, ca, cb, N);

    // --- concat (mean + BN2 apply folded) ---
    k_concat<<<cdiv((long long)G * ZD, 256), 256>>>(pool, cnt, ca, cb, rdkit, z, G);

    // --- MLP head ---
    k_fill<<<2, 256>>>(stats, 0.0f, 2 * HH);
    {
        dim3 grid(cdiv(G, 128), HH / 128);
        k_gemm128<true, false, true><<<grid, 256>>>(z, mW1, mb1, z1, nullptr, nullptr,
                                                    stats, G, ZD, HH);
    }
    k_bn_apply<HH><<<cdiv((long long)G * HH, 256), 256>>>(z1, stats, mg1, mbe1, G);

    k_fill<<<1, 256>>>(stats, 0.0f, 2 * H1);
    {
        dim3 grid(cdiv(G, 128), 1);
        k_gemm128<true, false, true><<<grid, 256>>>(z1, mW2, mb2, z2, nullptr, nullptr,
                                                    stats, G, HH, H1);
    }
    k_bn_apply<H1><<<cdiv((long long)G * H1, 256), 256>>>(z2, stats, mg2, mbe2, G);

    k_final<<<cdiv((long long)G * 32, 256), 256>>>(z2, mW3, mb3, out, G);
}